// round 10
// baseline (speedup 1.0000x reference)
#include <cuda_runtime.h>
#include <cstdint>

#define NIMG      32
#define IMH       512
#define IMW       512
#define PATCH     13
#define OWIDTH    500
#define OHEIGHT   500
#define SW        8          // output cols per thread
#define SH        16         // output rows per band (last band: 4)
#define NBANDS    32         // 31*16 + 4 = 500 output rows
#define NSTRIPS   63         // strips 0..62 active; strip 62 emits 4 cols
#define THREADS   64
#define EPSF      1e-5f

// per-(image,band) partials: [ccsum, S1, S2, S11, S22, S12]
__device__ float g_part[NIMG * NBANDS * 6];
__device__ unsigned int g_cnt[NIMG];   // zero-init; reset by finalizer each launch

__device__ __forceinline__ void load_row(const float* __restrict__ p,
                                         float v[20], bool tail) {
    const float4* q = reinterpret_cast<const float4*>(p);
#pragma unroll
    for (int i = 0; i < 5; i++) {
        if (tail && i == 4) {
            v[16] = v[17] = v[18] = v[19] = 0.f;
        } else {
            float4 t = __ldg(q + i);
            v[4*i+0] = t.x; v[4*i+1] = t.y; v[4*i+2] = t.z; v[4*i+3] = t.w;
        }
    }
}

// window-fill phase: add one row's horizontal 13-tap sums (5 quantities)
__device__ __forceinline__ void accum_add(float S0[SW], float S1[SW], float S2[SW],
                                          float S3[SW], float S4[SW],
                                          const float a[20], const float b[20]) {
    float h0 = 0.f, h1 = 0.f, h2 = 0.f, h3 = 0.f, h4 = 0.f;
#pragma unroll
    for (int k = 0; k < PATCH; k++) {
        float xa = a[k], xb = b[k];
        h0 += xa;
        h1 += xb;
        h2 = fmaf(xa, xa, h2);
        h3 = fmaf(xb, xb, h3);
        h4 = fmaf(xa, xb, h4);
    }
#pragma unroll
    for (int j = 0; j < SW; j++) {
        if (j > 0) {
            float xa = a[j + 12], xb = b[j + 12];
            float ya = a[j - 1],  yb = b[j - 1];
            h0 += xa - ya;
            h1 += xb - yb;
            h2 += fmaf(xa, xa, -(ya * ya));
            h3 += fmaf(xb, xb, -(yb * yb));
            h4 += fmaf(xa, xb, -(ya * yb));
        }
        S0[j] += h0; S1[j] += h1; S2[j] += h2; S3[j] += h3; S4[j] += h4;
    }
}

// steady-state: fused (incoming - departing) delta via g = i-o, s = i+o:
//   d(sum)   = window-sum g
//   d(sum^2) = window-sum g*s            (i^2 - o^2 = g*s)
//   d(cross) = 0.5 * window-sum (sa*gb + ga*sb)
// ga,sa,gb,sb arrays hold g/s after in-place forming.
__device__ __forceinline__ void accum_delta(float S0[SW], float S1[SW], float S2[SW],
                                            float S3[SW], float S4[SW],
                                            const float ga[20], const float sa[20],
                                            const float gb[20], const float sb[20]) {
    float t0 = 0.f, t1 = 0.f, t2 = 0.f, t3 = 0.f, t4 = 0.f;
#pragma unroll
    for (int k = 0; k < PATCH; k++) {
        t0 += ga[k];
        t1 += gb[k];
        t2 = fmaf(ga[k], sa[k], t2);
        t3 = fmaf(gb[k], sb[k], t3);
        t4 = fmaf(sa[k], gb[k], t4);
        t4 = fmaf(ga[k], sb[k], t4);
    }
#pragma unroll
    for (int j = 0; j < SW; j++) {
        if (j > 0) {
            const int n = j + 12, o = j - 1;
            t0 += ga[n] - ga[o];
            t1 += gb[n] - gb[o];
            t2 = fmaf(ga[n], sa[n], t2);  t2 = fmaf(-ga[o], sa[o], t2);
            t3 = fmaf(gb[n], sb[n], t3);  t3 = fmaf(-gb[o], sb[o], t3);
            t4 = fmaf(sa[n], gb[n], t4);  t4 = fmaf(ga[n], sb[n], t4);
            t4 = fmaf(-sa[o], gb[o], t4); t4 = fmaf(-ga[o], sb[o], t4);
        }
        S0[j] += t0; S1[j] += t1; S2[j] += t2; S3[j] += t3;
        S4[j] = fmaf(0.5f, t4, S4[j]);
    }
}

// Global-NCC partial sums over this thread's OWNED columns of one row.
__device__ __forceinline__ void accum_global(float gs[5], const float a[20],
                                             const float b[20], bool wide) {
    const int lim = wide ? 16 : SW;   // strip 62 owns cols 496..511
#pragma unroll
    for (int j = 0; j < 16; j++) {
        if (j >= lim) break;
        float xa = a[j], xb = b[j];
        gs[0] += xa; gs[1] += xb;
        gs[2] = fmaf(xa, xa, gs[2]);
        gs[3] = fmaf(xb, xb, gs[3]);
        gs[4] = fmaf(xa, xb, gs[4]);
    }
}

__global__ void __launch_bounds__(THREADS, 7)
ncc_fused_kernel(const float* __restrict__ x1, const float* __restrict__ x2,
                 float* __restrict__ out) {
    const int band = blockIdx.x;
    const int img  = blockIdx.y;
    const int t    = threadIdx.x;
    const bool active = (t < NSTRIPS);
    const bool wide   = (t == NSTRIPS - 1);   // owns cols 496..511 for global sums
    const bool tail   = wide;                 // must not load cols >= 512

    const int c0 = t * SW;
    const int r0 = band * SH;                 // last band: r0 = 496
    const int Eb = (OHEIGHT - r0) < SH ? (OHEIGHT - r0) : SH;   // emitted rows
    const int E  = PATCH + Eb - 1;            // total row events (fill 13 + delta E-13)
    int nv = OWIDTH - c0; if (nv > SW) nv = SW;
    const int nvalid = nv;

    const float* __restrict__ b1 = x1 + (size_t)img * IMH * IMW;
    const float* __restrict__ b2 = x2 + (size_t)img * IMH * IMW;

    float S0[SW], S1[SW], S2[SW], S3[SW], S4[SW];
#pragma unroll
    for (int j = 0; j < SW; j++) { S0[j]=0.f; S1[j]=0.f; S2[j]=0.f; S3[j]=0.f; S4[j]=0.f; }
    float gs[5] = {0.f, 0.f, 0.f, 0.f, 0.f};
    float ccacc = 0.f;

    const float N169 = 169.0f;
    const float EPS2 = 169.0f * 169.0f * EPSF;

    // emit one output row from current S (unnormalized form, n folded out)
    auto emit = [&]() {
#pragma unroll
        for (int j = 0; j < SW; j++) {
            if (j < nvalid) {
                float s1 = S0[j], s2 = S1[j];
                float u1 = fmaf(S2[j], N169, EPS2) - s1 * s1;
                float u2 = fmaf(S3[j], N169, EPS2) - s2 * s2;
                float A  = fmaf(S4[j], N169, -(s1 * s2));
                ccacc = fmaf(A, rsqrtf(u1 * u2), ccacc);
            }
        }
    };

    if (active) {
        float ia[20], ib[20], oa[20], ob[20];

        // ---- fill: first 13 input rows (always owned: 13 <= SH, and the last
        // band's E=16 events cover exactly its owned rows 496..511)
#pragma unroll 1
        for (int e = 0; e < PATCH; e++) {
            const int row = r0 + e;
            load_row(b1 + (size_t)row * IMW + c0, ia, tail);
            load_row(b2 + (size_t)row * IMW + c0, ib, tail);
            accum_add(S0, S1, S2, S3, S4, ia, ib);
            accum_global(gs, ia, ib, wide);
        }

        // ---- steady state: one fused delta event per remaining row
#pragma unroll 1
        for (int e = PATCH; e < E; e++) {
            const int rin  = r0 + e;
            const int rout = r0 + e - PATCH;
            // issue all loads first...
            load_row(b1 + (size_t)rin  * IMW + c0, ia, tail);
            load_row(b2 + (size_t)rin  * IMW + c0, ib, tail);
            load_row(b1 + (size_t)rout * IMW + c0, oa, tail);
            load_row(b2 + (size_t)rout * IMW + c0, ob, tail);

            // ...then emit the previous output row in the load shadow
            // (row e-13 needs S after events <= e-1 — exactly current S)
            emit();

            // global sums on raw incoming row (bands own their first SH rows;
            // last band's events all satisfy e < SH since E = 16 there)
            if (e < SH)
                accum_global(gs, ia, ib, wide);

            // form g/s in place: ia<-g_a, oa<-s_a, ib<-g_b, ob<-s_b
#pragma unroll
            for (int k = 0; k < 20; k++) {
                float ga = ia[k] - oa[k];
                float sa = ia[k] + oa[k];
                float gb = ib[k] - ob[k];
                float sb = ib[k] + ob[k];
                ia[k] = ga; oa[k] = sa; ib[k] = gb; ob[k] = sb;
            }
            accum_delta(S0, S1, S2, S3, S4, ia, oa, ib, ob);
        }

        // ---- last output row (Eb-1)
        emit();
    }

    // ---- deterministic block reduction of (ccacc, gs[0..4])
    float vals[6] = {ccacc, gs[0], gs[1], gs[2], gs[3], gs[4]};
#pragma unroll
    for (int off = 16; off > 0; off >>= 1) {
#pragma unroll
        for (int q = 0; q < 6; q++)
            vals[q] += __shfl_down_sync(0xffffffffu, vals[q], off);
    }
    __shared__ float red[THREADS / 32][6];
    __shared__ bool  is_last;
    const int w = t >> 5, l = t & 31;
    if (l == 0) {
#pragma unroll
        for (int q = 0; q < 6; q++) red[w][q] = vals[q];
    }
    __syncthreads();
    if (t == 0) {
        float* dst = g_part + ((size_t)img * NBANDS + band) * 6;
#pragma unroll
        for (int q = 0; q < 6; q++)
            dst[q] = red[0][q] + red[1][q];
        __threadfence();
        unsigned old = atomicAdd(&g_cnt[img], 1u);
        is_last = (old == NBANDS - 1);
    }
    __syncthreads();

    // ---- last arriving block for this image finalizes (fixed-order sums)
    if (is_last) {
        __threadfence();
        __shared__ float comp[6];
        if (t < 6) {
            const float* src = g_part + (size_t)img * NBANDS * 6;
            float acc = 0.f;
#pragma unroll 1
            for (int k = 0; k < NBANDS; k++)
                acc += src[k * 6 + t];
            comp[t] = acc;
        }
        __syncthreads();
        if (t == 0) {
            const float ccsum = comp[0];
            const float s1 = comp[1], s2 = comp[2];
            const float s11 = comp[3], s22 = comp[4], s12 = comp[5];
            const float invN = 1.0f / (float)(IMH * IMW);
            const float m1 = s1 * invN;
            const float m2 = s2 * invN;
            const float v1 = fmaf(s11, invN, -(m1 * m1)) + EPSF;
            const float v2 = fmaf(s22, invN, -(m2 * m2)) + EPSF;
            const float g  = fmaf(s12, invN, -(m1 * m2)) * rsqrtf(v1 * v2);
            const float p  = ccsum * (1.0f / (500.0f * 500.0f));  // n folded out
            out[img] = 0.5f * g + 0.5f * p;
            g_cnt[img] = 0;   // reset for next launch / graph replay
        }
    }
}

extern "C" void kernel_launch(void* const* d_in, const int* in_sizes, int n_in,
                              void* d_out, int out_size) {
    const float* x1 = (const float*)d_in[0];
    const float* x2 = (const float*)d_in[1];
    float* out = (float*)d_out;

    dim3 grid(NBANDS, NIMG);
    ncc_fused_kernel<<<grid, THREADS>>>(x1, x2, out);
}